// round 3
// baseline (speedup 1.0000x reference)
#include <cuda_runtime.h>
#include <cstdint>

#define DEC 256

// Fixed-slot partials: one float per group (G = 511 <= 1024). Deterministic.
__device__ float g_partials[1024];

__device__ __forceinline__ void pair_term(float oi, float ti, float2 u,
                                          float& acc) {
    float dt = ti - u.y;                       // t_i - t_j
    float dO = oi - u.x;                       // o_i - o_j
    // x = sign(dt) * dO via sign-bit XOR (one LOP3). dt==-0 gives wrong sign
    // but |dt|<=0.1 there so weight is 0 -> harmless.
    float x  = __uint_as_float(__float_as_uint(dO) ^
                               (__float_as_uint(dt) & 0x80000000u));
    float h  = fmaxf(x + 1.0f, 0.0f);          // hinge
    if (fabsf(dt) > 0.1f) acc += h;            // FSETP + predicated FADD
}

__global__ void __launch_bounds__(256)
rank_loss_groups(const float* __restrict__ inp, const float* __restrict__ tm) {
    __shared__ float2 sh[512];    // duplicated so index i+k needs no modulo
    __shared__ float  warpsum[8];

    const int g    = blockIdx.x;
    const int i    = threadIdx.x;
    const int base = g * DEC;

    const float oi = inp[base + i];
    const float ti = tm[base + i];
    float2 v; v.x = oi; v.y = ti;
    sh[i]       = v;
    sh[i + DEC] = v;
    __syncthreads();

    // Unordered pairs via cyclic offsets: k = 1..127 for every thread,
    // k = 128 for threads i < 128. Each unordered pair appears exactly once.
    float acc0 = 0.0f, acc1 = 0.0f;
    #pragma unroll 4
    for (int k = 1; k < 127; k += 2) {
        pair_term(oi, ti, sh[i + k],     acc0);
        pair_term(oi, ti, sh[i + k + 1], acc1);
    }
    pair_term(oi, ti, sh[i + 127], acc0);        // k = 127
    if (i < DEC / 2) {
        pair_term(oi, ti, sh[i + 128], acc1);    // k = 128 (half the threads)
    }

    // Block reduction (fixed order within warp/block).
    float s = acc0 + acc1;
    const int lane = i & 31;
    const int w    = i >> 5;
    #pragma unroll
    for (int off = 16; off; off >>= 1)
        s += __shfl_xor_sync(0xFFFFFFFFu, s, off);
    if (lane == 0) warpsum[w] = s;
    __syncthreads();
    if (w == 0) {
        float b = (lane < 8) ? warpsum[lane] : 0.0f;
        #pragma unroll
        for (int off = 4; off; off >>= 1)
            b += __shfl_xor_sync(0xFFFFFFFFu, b, off);
        if (lane == 0) g_partials[g] = b;
    }
}

__global__ void __launch_bounds__(512)
rank_loss_finalize(float* __restrict__ out, int G, float scale) {
    __shared__ float warpsum[16];
    const int tid = threadIdx.x;

    float s = 0.0f;
    for (int idx = tid; idx < G; idx += 512) s += g_partials[idx];

    const int lane = tid & 31;
    const int w    = tid >> 5;
    #pragma unroll
    for (int off = 16; off; off >>= 1)
        s += __shfl_xor_sync(0xFFFFFFFFu, s, off);
    if (lane == 0) warpsum[w] = s;
    __syncthreads();
    if (w == 0) {
        float b = (lane < 16) ? warpsum[lane] : 0.0f;
        #pragma unroll
        for (int off = 8; off; off >>= 1)
            b += __shfl_xor_sync(0xFFFFFFFFu, b, off);
        if (lane == 0) out[0] = b * scale;   // * 2 / N (symmetry doubling folded in)
    }
}

extern "C" void kernel_launch(void* const* d_in, const int* in_sizes, int n_in,
                              void* d_out, int out_size) {
    const float* inp = (const float*)d_in[0];   // input, [B,1] fp32
    const float* tm  = (const float*)d_in[1];   // gdt_ts, [B]  fp32

    const int B = in_sizes[0];
    const int K = B / DEC;
    const int G = K - 1;                        // reference skips the last group
    const double N = (double)G * DEC * (DEC - 1);
    const float scale = (float)(2.0 / N);       // x2: unordered -> ordered pairs

    rank_loss_groups<<<G, 256>>>(inp, tm);
    rank_loss_finalize<<<1, 512>>>((float*)d_out, G, scale);
}

// round 5
// speedup vs baseline: 1.1940x; 1.1940x over previous
#include <cuda_runtime.h>

#define DEC 256

// Fixed-slot per-group partials + completion ticket (self-resetting for graph replay).
__device__ float g_partials[1024];
__device__ int   g_counter = 0;

// Pad-swizzle for shared indexing: spreads the stride-4 (32B) lane pattern
// across banks. Strictly increasing -> injective; max phys = 511+31 = 542.
__device__ __forceinline__ int swz(int j) { return j + (j >> 4); }

__device__ __forceinline__ unsigned long long pack2(float lo, float hi) {
    unsigned long long r;
    asm("mov.b64 %0, {%1, %2};" : "=l"(r) : "f"(lo), "f"(hi));
    return r;
}

__device__ __forceinline__ void pair_term(unsigned long long own,
                                          unsigned long long w, float& acc) {
    // d = (o_i - o_j, t_i - t_j) in ONE packed add (w holds negated values)
    unsigned long long d;
    asm("add.rn.f32x2 %0, %1, %2;" : "=l"(d) : "l"(own), "l"(w));
    float dO, dt;
    asm("mov.b64 {%0, %1}, %2;" : "=f"(dO), "=f"(dt) : "l"(d));
    // x = sign(dt)*dO via sign-bit XOR (single LOP3); dt==+-0 case has weight 0.
    float x = __uint_as_float(__float_as_uint(dO) ^
                              (__float_as_uint(dt) & 0x80000000u));
    float h = fmaxf(x + 1.0f, 0.0f);
    if (fabsf(dt) > 0.1f) acc += h;
}

__global__ void __launch_bounds__(256)
rank_loss_fused(const float* __restrict__ inp, const float* __restrict__ tm,
                float* __restrict__ out, float scale) {
    __shared__ unsigned long long sh[544];   // negated (o,t), duplicated, padded
    __shared__ float warpsum[8];
    __shared__ int   s_isLast;

    const int g    = blockIdx.x;
    const int tid  = threadIdx.x;
    const int base = g * DEC;

    {
        float o = inp[base + tid];
        float t = tm[base + tid];
        unsigned long long nv = pack2(-o, -t);
        sh[swz(tid)]       = nv;
        sh[swz(tid + DEC)] = nv;
    }
    __syncthreads();

    // Thread decomposition: 4 k-range sets x 64 row-quads.
    const int s   = tid >> 6;          // k-range set 0..3
    const int tau = tid & 63;          // row-quad index
    const int b   = tau * 4;           // first owned row
    const int k0  = s * 32 + 1;        // k in [k0, k0+31]

    // Own rows packed (o, t).
    unsigned long long own0 = pack2(inp[base + b + 0], tm[base + b + 0]);
    unsigned long long own1 = pack2(inp[base + b + 1], tm[base + b + 1]);
    unsigned long long own2 = pack2(inp[base + b + 2], tm[base + b + 2]);
    unsigned long long own3 = pack2(inp[base + b + 3], tm[base + b + 3]);

    // Prime sliding window: w[r] = sh[b + k + r]
    unsigned long long w0 = sh[swz(b + k0 + 0)];
    unsigned long long w1 = sh[swz(b + k0 + 1)];
    unsigned long long w2 = sh[swz(b + k0 + 2)];
    unsigned long long w3 = sh[swz(b + k0 + 3)];

    float a0 = 0.0f, a1 = 0.0f, a2 = 0.0f, a3 = 0.0f;

    #pragma unroll
    for (int kk = 0; kk < 31; ++kk) {          // k = k0 .. k0+30, always active
        const int k = k0 + kk;
        pair_term(own0, w0, a0);
        pair_term(own1, w1, a1);
        pair_term(own2, w2, a2);
        pair_term(own3, w3, a3);
        w0 = w1; w1 = w2; w2 = w3;
        w3 = sh[swz(b + k + 4)];
    }
    // Epilogue k = k0+31 (= 32,64,96,128). Inactive only for s==3 && tau>=32
    // (k=128 counts rows < 128 only)  <=>  tid >= 224.
    if (tid < 224) {
        pair_term(own0, w0, a0);
        pair_term(own1, w1, a1);
        pair_term(own2, w2, a2);
        pair_term(own3, w3, a3);
    }

    // Block reduction (fixed order).
    float ssum = (a0 + a1) + (a2 + a3);
    const int lane = tid & 31;
    const int w    = tid >> 5;
    #pragma unroll
    for (int off = 16; off; off >>= 1)
        ssum += __shfl_xor_sync(0xFFFFFFFFu, ssum, off);
    if (lane == 0) warpsum[w] = ssum;
    __syncthreads();
    if (tid == 0) {
        float bsum = 0.0f;
        #pragma unroll
        for (int j = 0; j < 8; ++j) bsum += warpsum[j];
        g_partials[g] = bsum;
        __threadfence();
        int c = atomicAdd(&g_counter, 1);
        s_isLast = (c == (int)gridDim.x - 1);
    }
    __syncthreads();

    if (s_isLast) {
        const int G = gridDim.x;
        float v = 0.0f;
        for (int idx = tid; idx < G; idx += 256)
            v += *(volatile float*)&g_partials[idx];
        #pragma unroll
        for (int off = 16; off; off >>= 1)
            v += __shfl_xor_sync(0xFFFFFFFFu, v, off);
        __syncthreads();                 // warpsum reuse barrier
        if (lane == 0) warpsum[w] = v;
        __syncthreads();
        if (tid == 0) {
            float tot = 0.0f;
            #pragma unroll
            for (int j = 0; j < 8; ++j) tot += warpsum[j];
            out[0] = tot * scale;        // * 2/N (symmetry doubling folded in)
            g_counter = 0;               // reset for next graph replay
        }
    }
}

extern "C" void kernel_launch(void* const* d_in, const int* in_sizes, int n_in,
                              void* d_out, int out_size) {
    const float* inp = (const float*)d_in[0];   // input, [B,1] fp32
    const float* tm  = (const float*)d_in[1];   // gdt_ts, [B]  fp32

    const int B = in_sizes[0];
    const int K = B / DEC;
    const int G = K - 1;                        // reference skips the last group
    const double N = (double)G * DEC * (DEC - 1);
    const float scale = (float)(2.0 / N);       // x2: unordered -> ordered pairs

    rank_loss_fused<<<G, 256>>>(inp, tm, (float*)d_out, scale);
}